// round 2
// baseline (speedup 1.0000x reference)
#include <cuda_runtime.h>
#include <math.h>
#include <stdint.h>

#define LQ 256
#define BQ 64
#define DQ 1024
#define VQ 32000
#define MQ (LQ * BQ)          // 16384 rows for projections

// ---------------- scratch (static device globals; no allocation) ----------------
__device__ float g_x [LQ * BQ * DQ];   // current layer input / bw output
__device__ float g_h [LQ * BQ * DQ];   // fw output ("first")
__device__ float g_xi[LQ * BQ * DQ];
__device__ float g_xf[LQ * BQ * DQ];
__device__ float g_xc[LQ * BQ * DQ];
__device__ float g_cbuf[2 * BQ * DQ];  // double-buffered recurrent state
__device__ unsigned g_bar_count;       // zero-initialized
__device__ unsigned g_bar_gen;

// ---------------- embedding gather ----------------
__global__ __launch_bounds__(256) void embed_kernel(
    const int* __restrict__ xs, const float* __restrict__ emb, float* __restrict__ x)
{
    int i = blockIdx.x * 256 + threadIdx.x;     // over MQ*DQ/4 float4's
    int tokpos = i >> 8;                        // DQ/4 = 256 float4 per row
    int d4 = i & 255;
    int tok = xs[tokpos];
    tok = min(max(tok, 0), VQ - 1);
    ((float4*)x)[i] = ((const float4*)(emb + (size_t)tok * DQ))[d4];
}

__global__ __launch_bounds__(256) void zero_kernel(float* __restrict__ p, int n)
{
    int i = blockIdx.x * 256 + threadIdx.x;
    if (i < n) p[i] = 0.0f;
}

// ---------------- fp32 SGEMM + bias:  C[M,N] = A[M,K] @ W[K,N] + bias ----------------
// M=16384, N=K=1024 fixed. BM=BN=128, BK=8, 256 threads, 8x8 per thread.
#define GBM 128
#define GBN 128
#define GBK 8

__global__ __launch_bounds__(256) void sgemm_bias(
    const float* __restrict__ A, const float* __restrict__ W,
    const float* __restrict__ bias, float* __restrict__ C)
{
    __shared__ __align__(16) float As[GBK][GBM];   // transposed A tile
    __shared__ __align__(16) float Bs[GBK][GBN];

    const int tid = threadIdx.x;
    const int bx = blockIdx.x;                 // N tile index (0..7)
    const int by = blockIdx.y;                 // M tile index (0..127)

    const int arow = tid >> 1;                 // 0..127
    const int acol = (tid & 1) << 2;           // 0 or 4
    const int brow = tid >> 5;                 // 0..7
    const int bcol = (tid & 31) << 2;          // 0..124
    const int tr = tid >> 4;                   // 0..15
    const int tc = tid & 15;                   // 0..15

    const float* Aptr = A + (size_t)(by * GBM + arow) * DQ + acol;
    const float* Wptr = W + (size_t)brow * DQ + bx * GBN + bcol;

    float acc[8][8] = {};

    for (int kt = 0; kt < DQ; kt += GBK) {
        float4 av = *(const float4*)(Aptr + kt);
        As[acol + 0][arow] = av.x;
        As[acol + 1][arow] = av.y;
        As[acol + 2][arow] = av.z;
        As[acol + 3][arow] = av.w;
        *(float4*)&Bs[brow][bcol] = *(const float4*)(Wptr + (size_t)kt * DQ);
        __syncthreads();

        #pragma unroll
        for (int k = 0; k < GBK; k++) {
            float rm[8], rn[8];
            *(float4*)&rm[0] = *(const float4*)&As[k][tr * 8];
            *(float4*)&rm[4] = *(const float4*)&As[k][tr * 8 + 4];
            *(float4*)&rn[0] = *(const float4*)&Bs[k][tc * 8];
            *(float4*)&rn[4] = *(const float4*)&Bs[k][tc * 8 + 4];
            #pragma unroll
            for (int i = 0; i < 8; i++)
                #pragma unroll
                for (int j = 0; j < 8; j++)
                    acc[i][j] += rm[i] * rn[j];
        }
        __syncthreads();
    }

    float bv[8];
    *(float4*)&bv[0] = *(const float4*)(bias + bx * GBN + tc * 8);
    *(float4*)&bv[4] = *(const float4*)(bias + bx * GBN + tc * 8 + 4);

    #pragma unroll
    for (int i = 0; i < 8; i++) {
        int row = by * GBM + tr * 8 + i;
        float4 o0 = make_float4(acc[i][0] + bv[0], acc[i][1] + bv[1],
                                acc[i][2] + bv[2], acc[i][3] + bv[3]);
        float4 o1 = make_float4(acc[i][4] + bv[4], acc[i][5] + bv[5],
                                acc[i][6] + bv[6], acc[i][7] + bv[7]);
        float* cp = C + (size_t)row * DQ + bx * GBN + tc * 8;
        *(float4*)cp = o0;
        *(float4*)(cp + 4) = o1;
    }
}

// ---------------- persistent scan kernel ----------------
// 128 CTAs x 256 threads, all co-resident. CTA owns 8 output columns (same n for
// Wic and Wfc), weight slices live in dynamic SMEM for the whole scan.
#define NB_SCAN 128
#define SCAN_SMEM_BYTES ((DQ * 16 + BQ * 16) * 4)   // 69632

__device__ __forceinline__ void grid_sync()
{
    __syncthreads();
    if (threadIdx.x == 0) {
        __threadfence();
        volatile unsigned* genp = &g_bar_gen;
        unsigned gen = *genp;
        unsigned arrived = atomicAdd(&g_bar_count, 1u);
        if (arrived == NB_SCAN - 1) {
            g_bar_count = 0;
            __threadfence();
            *genp = gen + 1;
        } else {
            while (*genp == gen) { __nanosleep(64); }
        }
    }
    __syncthreads();
}

__global__ __launch_bounds__(256) void scan_kernel(
    const float* __restrict__ x,  const float* __restrict__ xi,
    const float* __restrict__ xf, const float* __restrict__ xc,
    const float* __restrict__ Wic, const float* __restrict__ Wfc,
    float* __restrict__ cbuf,     // [2][BQ*DQ]
    float* __restrict__ h, int reverse)
{
    extern __shared__ __align__(16) float smem[];
    float* Ws = smem;               // [DQ][16]: cols 0..7 = Wic slice, 8..15 = Wfc slice
    float* uv = smem + DQ * 16;     // [BQ][16]: u at [b][0..7], v at [b][8..15]

    const int tid = threadIdx.x;
    const int n0 = blockIdx.x * 8;

    for (int idx = tid; idx < DQ * 8; idx += 256) {
        int k = idx >> 3, n = idx & 7;
        Ws[k * 16 + n]     = Wic[(size_t)k * DQ + n0 + n];
        Ws[k * 16 + 8 + n] = Wfc[(size_t)k * DQ + n0 + n];
    }
    __syncthreads();

    const int q = tid & 3;          // quadrant: 0,1 -> u cols; 2,3 -> v cols
    const int b = tid >> 2;         // 0..63
    const float4* wq = (const float4*)Ws + q;   // Ws[k][q*4] = float4 index k*4+q

    for (int step = 0; step < LQ; step++) {
        const int t = reverse ? (LQ - 1 - step) : step;
        const float* cprev = cbuf + (step & 1) * (BQ * DQ);
        float* cnext = cbuf + ((step + 1) & 1) * (BQ * DQ);

        float a0 = 0.f, a1 = 0.f, a2 = 0.f, a3 = 0.f;
        const float4* crow = (const float4*)(cprev + (size_t)b * DQ);
        #pragma unroll 4
        for (int k4 = 0; k4 < DQ / 4; k4++) {
            float4 cv = __ldcg(crow + k4);
            float4 w0 = wq[(4 * k4 + 0) * 4];
            float4 w1 = wq[(4 * k4 + 1) * 4];
            float4 w2 = wq[(4 * k4 + 2) * 4];
            float4 w3 = wq[(4 * k4 + 3) * 4];
            a0 += cv.x * w0.x; a1 += cv.x * w0.y; a2 += cv.x * w0.z; a3 += cv.x * w0.w;
            a0 += cv.y * w1.x; a1 += cv.y * w1.y; a2 += cv.y * w1.z; a3 += cv.y * w1.w;
            a0 += cv.z * w2.x; a1 += cv.z * w2.y; a2 += cv.z * w2.z; a3 += cv.z * w2.w;
            a0 += cv.w * w3.x; a1 += cv.w * w3.y; a2 += cv.w * w3.z; a3 += cv.w * w3.w;
        }
        uv[b * 16 + q * 4 + 0] = a0;
        uv[b * 16 + q * 4 + 1] = a1;
        uv[b * 16 + q * 4 + 2] = a2;
        uv[b * 16 + q * 4 + 3] = a3;
        __syncthreads();

        // elementwise update: 64 b x 8 n = 512 outputs, 2 per thread
        #pragma unroll
        for (int rep = 0; rep < 2; rep++) {
            int rr = tid + rep * 256;
            int bb = rr >> 3, nn = rr & 7;
            int gn = n0 + nn;
            size_t off = ((size_t)t * BQ + bb) * DQ + gn;
            float uu = uv[bb * 16 + nn];
            float vv = uv[bb * 16 + 8 + nn];
            float iv = 1.0f / (1.0f + expf(-(xi[off] + uu)));
            float fv = 1.0f / (1.0f + expf(-(xf[off] + vv)));
            float cold = __ldcg(cprev + (size_t)bb * DQ + gn);
            float cn = iv * xc[off] + fv * cold;
            cnext[(size_t)bb * DQ + gn] = cn;
            h[off] = tanhf(cn) + x[off];
        }
        grid_sync();
    }
}

// ---------------- launcher ----------------
extern "C" void kernel_launch(void* const* d_in, const int* in_sizes, int n_in,
                              void* d_out, int out_size)
{
    (void)in_sizes; (void)n_in; (void)out_size;

    cudaFuncSetAttribute(scan_kernel, cudaFuncAttributeMaxDynamicSharedMemorySize,
                         SCAN_SMEM_BYTES);

    const int*   xs  = (const int*)d_in[0];
    const float* emb = (const float*)d_in[1];
    const float* P[16];
    for (int i = 0; i < 16; i++) P[i] = (const float*)d_in[2 + i];
    // P: 0=fw_Wix 1=fw_Wic 2=fw_Wfx 3=fw_Wfc 4=fw_Wcx 5=fw_bi 6=fw_bf 7=fw_bc
    //    8=bw_Wix 9=bw_Wic 10=bw_Wfx 11=bw_Wfc 12=bw_Wcx 13=bw_bi 14=bw_bf 15=bw_bc

    float *px, *ph, *pxi, *pxf, *pxc, *pcb;
    cudaGetSymbolAddress((void**)&px,  g_x);
    cudaGetSymbolAddress((void**)&ph,  g_h);
    cudaGetSymbolAddress((void**)&pxi, g_xi);
    cudaGetSymbolAddress((void**)&pxf, g_xf);
    cudaGetSymbolAddress((void**)&pxc, g_xc);
    cudaGetSymbolAddress((void**)&pcb, g_cbuf);
    float* out = (float*)d_out;

    embed_kernel<<<MQ * DQ / 4 / 256, 256>>>(xs, emb, px);
    zero_kernel<<<(2 * BQ * DQ + 255) / 256, 256>>>(pcb, 2 * BQ * DQ);

    dim3 ggrid(DQ / GBN, MQ / GBM);   // (8, 128)
    for (int layer = 0; layer < 2; layer++) {
        // forward direction
        sgemm_bias<<<ggrid, 256>>>(px, P[0], P[5], pxi);
        sgemm_bias<<<ggrid, 256>>>(px, P[2], P[6], pxf);
        sgemm_bias<<<ggrid, 256>>>(px, P[4], P[7], pxc);
        scan_kernel<<<NB_SCAN, 256, SCAN_SMEM_BYTES>>>(px, pxi, pxf, pxc,
                                                       P[1], P[3], pcb, ph, 0);
        // backward direction
        sgemm_bias<<<ggrid, 256>>>(ph, P[8],  P[13], pxi);
        sgemm_bias<<<ggrid, 256>>>(ph, P[10], P[14], pxf);
        sgemm_bias<<<ggrid, 256>>>(ph, P[12], P[15], pxc);
        float* ho = (layer == 1) ? out : px;
        scan_kernel<<<NB_SCAN, 256, SCAN_SMEM_BYTES>>>(ph, pxi, pxf, pxc,
                                                       P[9], P[11], pcb, ho, 1);
    }
}